// round 2
// baseline (speedup 1.0000x reference)
#include <cuda_runtime.h>
#include <cstdint>

// ---------------- problem constants ----------------
#define Bsz   16384
#define Sdim  256
#define Edim  128
#define Hdim  128
#define Ntask 34
#define TEMP_INV 10.0f

#define M_TILE  128
#define THREADS 256
#define KC      32
#define LDA_CH  36    // A chunk row stride (floats), 36%32=4 -> conflict-free frag loads
#define LDB_CH  136   // B chunk row stride, 136%32=8 -> conflict-free frag loads
#define LDH     132   // resident h row stride, 132%32=4 -> conflict-free

#define ABUF_ELEMS (M_TILE * LDA_CH)   // 4608
#define BBUF_ELEMS (KC * LDB_CH)       // 4352
#define SMEM_FLOATS (2*ABUF_ELEMS + 2*BBUF_ELEMS + M_TILE*LDH + 2*M_TILE*Ntask + 4*M_TILE + 2*M_TILE)
#define SMEM_BYTES (SMEM_FLOATS * 4)   // 177,152 B

// ---------------- device scratch (no allocations allowed) ----------------
__device__ float g_state[Bsz * Sdim];          // tf32-rounded state
__device__ float g_W1[Ntask * Sdim * Hdim];    // tf32-rounded weights
__device__ float g_W2[Ntask * Hdim * Hdim];
__device__ float g_W3[Ntask * Hdim * Edim];
__device__ float g_langn[Ntask * Edim];        // normalized lang_emb

// ---------------- helpers ----------------
__device__ __forceinline__ void cp16(float* dst, const float* src) {
    unsigned s = (unsigned)__cvta_generic_to_shared(dst);
    asm volatile("cp.async.cg.shared.global [%0], [%1], 16;\n" :: "r"(s), "l"(src));
}
#define CP_COMMIT()  asm volatile("cp.async.commit_group;\n" ::: "memory")
#define CP_WAIT1()   asm volatile("cp.async.wait_group 1;\n" ::: "memory")
#define CP_WAIT0()   asm volatile("cp.async.wait_group 0;\n" ::: "memory")

__device__ __forceinline__ void mma8(float& c0, float& c1, float& c2, float& c3,
                                     uint32_t a0, uint32_t a1, uint32_t a2, uint32_t a3,
                                     uint32_t b0, uint32_t b1) {
    asm volatile("mma.sync.aligned.m16n8k8.row.col.f32.tf32.tf32.f32 "
                 "{%0,%1,%2,%3},{%4,%5,%6,%7},{%8,%9},{%0,%1,%2,%3};\n"
                 : "+f"(c0), "+f"(c1), "+f"(c2), "+f"(c3)
                 : "r"(a0), "r"(a1), "r"(a2), "r"(a3), "r"(b0), "r"(b1));
}

__device__ __forceinline__ float quad_sum(float v) {
    v += __shfl_xor_sync(0xffffffffu, v, 1);
    v += __shfl_xor_sync(0xffffffffu, v, 2);
    return v;
}

__device__ __forceinline__ float to_tf32(float x) {
    uint32_t u;
    asm("cvt.rna.tf32.f32 %0, %1;" : "=r"(u) : "f"(x));
    return __uint_as_float(u);
}

// load a [128 x 32] A chunk (rows of the batch tile) into abuf
__device__ __forceinline__ void load_chA(float* ab, const float* Ag, int kc, int tid) {
    for (int c = tid; c < 1024; c += THREADS) {
        int row = c >> 3, seg = c & 7;
        cp16(ab + row * LDA_CH + seg * 4, Ag + (size_t)row * Sdim + kc * KC + seg * 4);
    }
}
// load a [32 x 128] B chunk (k rows of a weight matrix) into bbuf
__device__ __forceinline__ void load_chB(float* bb, const float* Bg, int kc, int tid) {
    for (int c = tid; c < 1024; c += THREADS) {
        int row = c >> 5, seg = c & 31;
        cp16(bb + row * LDB_CH + seg * 4, Bg + (size_t)(kc * KC + row) * Hdim + seg * 4);
    }
}

// one KC=32 slab of mma: C[128x128] += A[128x32] * B[32x128]
__device__ __forceinline__ void compute_k32(const float* __restrict__ A, int lda, int k0,
                                            const float* __restrict__ Bc,
                                            float (&acc)[2][8][4],
                                            int wm, int wn, int grp, int tig) {
#pragma unroll
    for (int ks = 0; ks < 4; ++ks) {
        uint32_t a[2][4];
#pragma unroll
        for (int t = 0; t < 2; ++t) {
            const float* Ap = A + (wm * 32 + t * 16 + grp) * lda + k0 + ks * 8 + tig;
            a[t][0] = __float_as_uint(Ap[0]);
            a[t][1] = __float_as_uint(Ap[8 * lda]);
            a[t][2] = __float_as_uint(Ap[4]);
            a[t][3] = __float_as_uint(Ap[8 * lda + 4]);
        }
        const float* Bp = Bc + (ks * 8 + tig) * LDB_CH + wn * 64 + grp;
#pragma unroll
        for (int j = 0; j < 8; ++j) {
            uint32_t b0 = __float_as_uint(Bp[j * 8]);
            uint32_t b1 = __float_as_uint(Bp[4 * LDB_CH + j * 8]);
            mma8(acc[0][j][0], acc[0][j][1], acc[0][j][2], acc[0][j][3],
                 a[0][0], a[0][1], a[0][2], a[0][3], b0, b1);
            mma8(acc[1][j][0], acc[1][j][1], acc[1][j][2], acc[1][j][3],
                 a[1][0], a[1][1], a[1][2], a[1][3], b0, b1);
        }
    }
}

// GEMM with A resident in smem, B streamed (double-buffered)
__device__ __forceinline__ void gemm_streamB(const float* __restrict__ Bg, int K,
                                             const float* __restrict__ A, int lda,
                                             float* bbuf, float (&acc)[2][8][4],
                                             int tid, int wm, int wn, int grp, int tig) {
    const int nch = K / KC;
    load_chB(bbuf, Bg, 0, tid);
    CP_COMMIT();
#pragma unroll 1
    for (int kc = 0; kc < nch; ++kc) {
        int cur = kc & 1;
        if (kc + 1 < nch) {
            load_chB(bbuf + (cur ^ 1) * BBUF_ELEMS, Bg, kc + 1, tid);
            CP_COMMIT();
            CP_WAIT1();
        } else {
            CP_WAIT0();
        }
        __syncthreads();
        compute_k32(A, lda, kc * KC, bbuf + cur * BBUF_ELEMS, acc, wm, wn, grp, tig);
        __syncthreads();
    }
}

// ---------------- pre-pass kernels ----------------
__global__ void cvt_tf32_kernel(const float* __restrict__ src, float* __restrict__ dst, int n) {
    int i = blockIdx.x * blockDim.x + threadIdx.x;
    if (i < n) dst[i] = to_tf32(src[i]);
}

__global__ void langn_kernel(const float* __restrict__ lang, float* __restrict__ dst) {
    int nidx = blockIdx.x, t = threadIdx.x;  // 128 threads per task row
    float v = lang[nidx * Edim + t];
    float s = v * v;
#pragma unroll
    for (int off = 16; off; off >>= 1) s += __shfl_xor_sync(0xffffffffu, s, off);
    __shared__ float red[4];
    if ((t & 31) == 0) red[t >> 5] = s;
    __syncthreads();
    float tot = red[0] + red[1] + red[2] + red[3];
    float nrm = fmaxf(sqrtf(tot), 1e-8f);
    dst[nidx * Edim + t] = v / nrm;
}

// ---------------- fused main kernel ----------------
__global__ __launch_bounds__(THREADS, 1)
void fused_kernel(const float* __restrict__ state_raw,
                  const int* __restrict__ task_id,
                  const float* __restrict__ prior,
                  const float* __restrict__ b1g,
                  const float* __restrict__ b2g,
                  const float* __restrict__ b3g,
                  float* __restrict__ out) {
    extern __shared__ __align__(16) float sm[];
    float* abuf  = sm;                           // 2*4608
    float* bbuf  = abuf + 2 * ABUF_ELEMS;        // 2*4352
    float* h_s   = bbuf + 2 * BBUF_ELEMS;        // 128*132
    float* p_s   = h_s + M_TILE * LDH;           // 128*34 softmax(prior)
    float* cos_s = p_s + M_TILE * Ntask;         // 128*34
    float* rpart = cos_s + M_TILE * Ntask;       // 2*128
    float* cpart = rpart + 2 * M_TILE;           // 2*128
    float* invn  = cpart + 2 * M_TILE;           // 128
    int*   tids  = (int*)(invn + M_TILE);        // 128

    const int tid  = threadIdx.x;
    const int bM   = blockIdx.x * M_TILE;
    const int lane = tid & 31;
    const int warp = tid >> 5;
    const int wm = warp >> 1, wn = warp & 1;
    const int grp = lane >> 2, tig = lane & 3;

    float* out_rep  = out;
    float* out_logp = out + (size_t)Bsz * (Sdim + Edim);
    float* out_tgt  = out_logp + (size_t)Bsz * Ntask;
    float* out_lat  = out_tgt + (size_t)Bsz * Edim;

    // ---- prologue: task ids + softmax(prior) ----
    if (tid < M_TILE) {
        tids[tid] = task_id[bM + tid];
        const float* pr = prior + (size_t)(bM + tid) * Ntask;
        float mx = -1e30f;
        for (int i = 0; i < Ntask; ++i) mx = fmaxf(mx, pr[i]);
        float s = 0.f;
        for (int i = 0; i < Ntask; ++i) s += expf(pr[i] - mx);
        float inv = 1.0f / s;
        for (int i = 0; i < Ntask; ++i) p_s[tid * Ntask + i] = expf(pr[i] - mx) * inv;
    }

    float lat[2][8][4];
#pragma unroll
    for (int t = 0; t < 2; ++t)
#pragma unroll
        for (int j = 0; j < 8; ++j)
#pragma unroll
            for (int i = 0; i < 4; ++i) lat[t][j][i] = 0.f;

    __syncthreads();

#pragma unroll 1
    for (int n = 0; n < Ntask; ++n) {
        float acc[2][8][4];
#pragma unroll
        for (int t = 0; t < 2; ++t)
#pragma unroll
            for (int j = 0; j < 8; ++j)
#pragma unroll
                for (int i = 0; i < 4; ++i) acc[t][j][i] = 0.f;

        // ---------- GEMM1: h1 = relu(state @ W1[n] + b1[n]) ----------
        {
            const float* Ag = g_state + (size_t)bM * Sdim;
            const float* Bg = g_W1 + (size_t)n * (Sdim * Hdim);
            load_chA(abuf, Ag, 0, tid);
            load_chB(bbuf, Bg, 0, tid);
            CP_COMMIT();
            const int nch = Sdim / KC;  // 8
#pragma unroll 1
            for (int kc = 0; kc < nch; ++kc) {
                int cur = kc & 1;
                if (kc + 1 < nch) {
                    load_chA(abuf + (cur ^ 1) * ABUF_ELEMS, Ag, kc + 1, tid);
                    load_chB(bbuf + (cur ^ 1) * BBUF_ELEMS, Bg, kc + 1, tid);
                    CP_COMMIT();
                    CP_WAIT1();
                } else {
                    CP_WAIT0();
                }
                __syncthreads();
                compute_k32(abuf + cur * ABUF_ELEMS, LDA_CH, 0,
                            bbuf + cur * BBUF_ELEMS, acc, wm, wn, grp, tig);
                __syncthreads();
            }
        }
        // bias + relu -> h (as tf32)
        {
            const float* bb = b1g + n * Hdim;
#pragma unroll
            for (int t = 0; t < 2; ++t)
#pragma unroll
                for (int j = 0; j < 8; ++j)
#pragma unroll
                    for (int i = 0; i < 4; ++i) {
                        int row = wm * 32 + t * 16 + (i >> 1) * 8 + grp;
                        int col = wn * 64 + j * 8 + tig * 2 + (i & 1);
                        float v = fmaxf(acc[t][j][i] + __ldg(bb + col), 0.f);
                        h_s[row * LDH + col] = to_tf32(v);
                        acc[t][j][i] = 0.f;
                    }
        }
        // ---------- GEMM2 ----------
        gemm_streamB(g_W2 + (size_t)n * (Hdim * Hdim), Hdim, h_s, LDH, bbuf, acc,
                     tid, wm, wn, grp, tig);
        {
            const float* bb = b2g + n * Hdim;
#pragma unroll
            for (int t = 0; t < 2; ++t)
#pragma unroll
                for (int j = 0; j < 8; ++j)
#pragma unroll
                    for (int i = 0; i < 4; ++i) {
                        int row = wm * 32 + t * 16 + (i >> 1) * 8 + grp;
                        int col = wn * 64 + j * 8 + tig * 2 + (i & 1);
                        float v = fmaxf(acc[t][j][i] + __ldg(bb + col), 0.f);
                        h_s[row * LDH + col] = to_tf32(v);
                        acc[t][j][i] = 0.f;
                    }
        }
        __syncthreads();
        // ---------- GEMM3: q = h2 @ W3[n] + b3[n] ----------
        gemm_streamB(g_W3 + (size_t)n * (Hdim * Edim), Hdim, h_s, LDH, bbuf, acc,
                     tid, wm, wn, grp, tig);
        {
            const float* bb = b3g + n * Edim;
#pragma unroll
            for (int t = 0; t < 2; ++t)
#pragma unroll
                for (int j = 0; j < 8; ++j)
#pragma unroll
                    for (int i = 0; i < 4; ++i) {
                        int col = wn * 64 + j * 8 + tig * 2 + (i & 1);
                        acc[t][j][i] += __ldg(bb + col);
                    }
        }

        // ---------- epilogue for task n ----------
        // row sum of squares (deterministic: quad shfl + 2-warp smem partials)
        float pr4[4] = {0.f, 0.f, 0.f, 0.f};
#pragma unroll
        for (int t = 0; t < 2; ++t)
#pragma unroll
            for (int j = 0; j < 8; ++j)
#pragma unroll
                for (int i = 0; i < 4; ++i)
                    pr4[t * 2 + (i >> 1)] += acc[t][j][i] * acc[t][j][i];
#pragma unroll
        for (int k = 0; k < 4; ++k) pr4[k] = quad_sum(pr4[k]);
        if (tig == 0) {
#pragma unroll
            for (int k = 0; k < 4; ++k) {
                int row = wm * 32 + (k >> 1) * 16 + (k & 1) * 8 + grp;
                rpart[wn * M_TILE + row] = pr4[k];
            }
        }
        __syncthreads();
        if (tid < M_TILE) invn[tid] = rsqrtf(rpart[tid] + rpart[M_TILE + tid]);
        __syncthreads();

        float cp4[4] = {0.f, 0.f, 0.f, 0.f};
#pragma unroll
        for (int t = 0; t < 2; ++t)
#pragma unroll
            for (int i2 = 0; i2 < 2; ++i2) {
                int row = wm * 32 + t * 16 + i2 * 8 + grp;
                float iv = invn[row];
                int tt = tids[row];
                float pw = p_s[row * Ntask + n];
                const float* lrow = g_langn + tt * Edim;
                bool hit = (tt == n);
                float* tgt = out_tgt + (size_t)(bM + row) * Edim;
#pragma unroll
                for (int j = 0; j < 8; ++j)
#pragma unroll
                    for (int ih = 0; ih < 2; ++ih) {
                        int i = i2 * 2 + ih;
                        int col = wn * 64 + j * 8 + tig * 2 + ih;
                        float qn = acc[t][j][i] * iv;
                        acc[t][j][i] = qn;
                        cp4[t * 2 + i2] += qn * __ldg(lrow + col);
                        lat[t][j][i] += qn * pw;
                        if (hit) tgt[col] = qn;
                    }
            }
#pragma unroll
        for (int k = 0; k < 4; ++k) cp4[k] = quad_sum(cp4[k]);
        if (tig == 0) {
#pragma unroll
            for (int k = 0; k < 4; ++k) {
                int row = wm * 32 + (k >> 1) * 16 + (k & 1) * 8 + grp;
                cpart[wn * M_TILE + row] = cp4[k];
            }
        }
        __syncthreads();
        if (tid < M_TILE) cos_s[tid * Ntask + n] = cpart[tid] + cpart[M_TILE + tid];
        __syncthreads();
    }

    // ---------- final epilogue ----------
    if (tid < M_TILE) {
        int rowg = bM + tid;
        const float* cr = cos_s + tid * Ntask;
        float mx = -1e30f;
        for (int nn = 0; nn < Ntask; ++nn) mx = fmaxf(mx, cr[nn] * TEMP_INV);
        float s = 0.f;
        for (int nn = 0; nn < Ntask; ++nn) s += expf(cr[nn] * TEMP_INV - mx);
        float lse = logf(s);
        float* op = out_logp + (size_t)rowg * Ntask;
        for (int nn = 0; nn < Ntask; ++nn) op[nn] = cr[nn] * TEMP_INV - mx - lse;
    }
    // latent_vec + rep_vec latent half
#pragma unroll
    for (int t = 0; t < 2; ++t)
#pragma unroll
        for (int j = 0; j < 8; ++j)
#pragma unroll
            for (int i = 0; i < 4; ++i) {
                int row = wm * 32 + t * 16 + (i >> 1) * 8 + grp;
                int col = wn * 64 + j * 8 + tig * 2 + (i & 1);
                float v = lat[t][j][i];
                size_t rg = (size_t)(bM + row);
                out_lat[rg * Edim + col] = v;
                out_rep[rg * (Sdim + Edim) + Sdim + col] = v;
            }
    // rep_vec state half (original fp32 state)
    for (int idx = tid; idx < M_TILE * Sdim; idx += THREADS) {
        int r = idx >> 8, c = idx & 255;
        out_rep[(size_t)(bM + r) * (Sdim + Edim) + c] =
            state_raw[(size_t)(bM + r) * Sdim + c];
    }
}

// ---------------- launch ----------------
extern "C" void kernel_launch(void* const* d_in, const int* in_sizes, int n_in,
                              void* d_out, int out_size) {
    const float* state = (const float*)d_in[0];
    const int*   task  = (const int*)d_in[1];
    const float* prior = (const float*)d_in[2];
    const float* W1    = (const float*)d_in[3];
    const float* b1    = (const float*)d_in[4];
    const float* W2    = (const float*)d_in[5];
    const float* b2    = (const float*)d_in[6];
    const float* W3    = (const float*)d_in[7];
    const float* b3    = (const float*)d_in[8];
    const float* lang  = (const float*)d_in[9];
    float* out = (float*)d_out;

    float *gs, *gw1, *gw2, *gw3, *gl;
    cudaGetSymbolAddress((void**)&gs,  g_state);
    cudaGetSymbolAddress((void**)&gw1, g_W1);
    cudaGetSymbolAddress((void**)&gw2, g_W2);
    cudaGetSymbolAddress((void**)&gw3, g_W3);
    cudaGetSymbolAddress((void**)&gl,  g_langn);

    int n1 = Bsz * Sdim;
    cvt_tf32_kernel<<<(n1 + 255) / 256, 256>>>(state, gs, n1);
    int n2 = Ntask * Sdim * Hdim;
    cvt_tf32_kernel<<<(n2 + 255) / 256, 256>>>(W1, gw1, n2);
    int n3 = Ntask * Hdim * Hdim;
    cvt_tf32_kernel<<<(n3 + 255) / 256, 256>>>(W2, gw2, n3);
    int n4 = Ntask * Hdim * Edim;
    cvt_tf32_kernel<<<(n4 + 255) / 256, 256>>>(W3, gw3, n4);
    langn_kernel<<<Ntask, 128>>>(lang, gl);

    cudaFuncSetAttribute(fused_kernel, cudaFuncAttributeMaxDynamicSharedMemorySize, SMEM_BYTES);
    fused_kernel<<<Bsz / M_TILE, THREADS, SMEM_BYTES>>>(state, task, prior, b1, b2, b3, out);
}